// round 8
// baseline (speedup 1.0000x reference)
#include <cuda_runtime.h>
#include <cuda_bf16.h>
#include <cstdint>

typedef __nv_bfloat16 bf16;

#define STAGES 3
#define STAGE_BYTES 49152               // A 256x128B + B 128x128B
#define SMEM_ALLOC (1024 + STAGES*STAGE_BYTES)

#define BIG 8388608ULL
#define MB1 1048576ULL

// bf16 arena: FIN 0-6, FP 6-12, Q 12-18, K 18-24, VT 24-30, QS1 30-32, P 32-38, W 38..+24MB1
__device__ bf16  g_bf[38ULL*BIG + 24ULL*MB1];
// f32 arena: S 0-3, T 3-4, Qf2 4-5, Qf3 5-6
__device__ float g_f[6ULL*BIG];

__device__ __forceinline__ uint32_t su32(const void* p){ return (uint32_t)__cvta_generic_to_shared(p); }
__device__ __forceinline__ void cp16(uint32_t s, const void* g){
    asm volatile("cp.async.cg.shared.global [%0], [%1], 16;"
        :: "r"(s), "l"((unsigned long long)__cvta_generic_to_global(g)) : "memory");
}
__device__ __forceinline__ uint32_t pk(bf16 a, bf16 b){
    return (uint32_t)__bfloat16_as_ushort(a) | ((uint32_t)__bfloat16_as_ushort(b) << 16);
}
__device__ __forceinline__ uint32_t swz(uint32_t o){ return o ^ ((o >> 3) & 0x70); }

__device__ __forceinline__ void ldsm4(uint32_t* r, uint32_t addr){
    asm volatile("ldmatrix.sync.aligned.m8n8.x4.shared.b16 {%0,%1,%2,%3}, [%4];"
        : "=r"(r[0]), "=r"(r[1]), "=r"(r[2]), "=r"(r[3]) : "r"(addr));
}
__device__ __forceinline__ void mma16816(float* d, const uint32_t* a, const uint32_t* b){
    asm volatile("mma.sync.aligned.m16n8k16.row.col.f32.bf16.bf16.f32 "
        "{%0,%1,%2,%3}, {%4,%5,%6,%7}, {%8,%9}, {%0,%1,%2,%3};"
        : "+f"(d[0]), "+f"(d[1]), "+f"(d[2]), "+f"(d[3])
        : "r"(a[0]), "r"(a[1]), "r"(a[2]), "r"(a[3]), "r"(b[0]), "r"(b[1]));
}

struct GDesc {
    const bf16 *Ah, *Al, *Bh, *Bl;
    long long sA, sB;
    const float* bias;
    const float* AccC; long long sAcc;
    float* Cf; long long sCf; int ldcf;
    bf16 *Chi, *Clo;
    int trans, relu, wf32, wsplit;
};
struct GTable { GDesc d[9]; int nb; };

// load one k-step of fragments for 64x64 warp tile
__device__ __forceinline__ void ldfr(uint32_t (*afb)[4], uint32_t (*bfb)[4],
    uint32_t sa, uint32_t sb, int kb, int wm, int wn, int r8, int sg)
{
#pragma unroll
    for (int mt = 0; mt < 4; mt++) {
        int row = wm + mt*16 + r8 + ((sg & 1) << 3);
        ldsm4(afb[mt], sa + swz((uint32_t)(row*128 + kb + ((sg >> 1) << 4))));
    }
#pragma unroll
    for (int nq = 0; nq < 4; nq++) {
        int row = wn + nq*16 + r8 + ((sg >> 1) << 3);
        ldsm4(bfb[nq], sb + swz((uint32_t)(row*128 + kb + ((sg & 1) << 4))));
    }
}

// batched 3-term split GEMM: C = Ah Bh^T + Al Bh^T + Ah Bl^T (+AccC) (+bias,relu)
// CTA tile 256x128, 256 threads, 8 warps (4 M x 2 N), warp tile 64x64
__global__ void __launch_bounds__(256, 1) gemm_b(GTable t)
{
    extern __shared__ char smem[];
    const uint32_t tbase = (su32(smem) + 1023u) & ~1023u;
    const int tid = threadIdx.x, wid = tid >> 5, lane = tid & 31;
    const int di = blockIdx.z / t.nb, zb = blockIdx.z - di * t.nb;
    const GDesc g = t.d[di];
    const int m0 = blockIdx.y * 256, n0 = blockIdx.x * 128;
    const int wm = (wid & 3) * 64, wn = (wid >> 2) * 64;
    const int r8 = lane & 7, sg = lane >> 3;

    const bf16* Ah = g.Ah + (long long)zb * g.sA;
    const bf16* Al = g.Al + (long long)zb * g.sA;
    const bf16* Bh = g.Bh + (long long)zb * g.sB;
    const bf16* Bl = g.Bl + (long long)zb * g.sB;
    const bf16* sgA[3] = { Ah, Al, Ah };
    const bf16* sgB[3] = { Bh, Bh, Bl };

    float acc[4][8][4];
#pragma unroll
    for (int a = 0; a < 4; a++)
#pragma unroll
        for (int b = 0; b < 8; b++)
#pragma unroll
            for (int c = 0; c < 4; c++) acc[a][b][c] = 0.f;

    auto load_chunk = [&](int j) {
        const int seg = j >> 4, k0 = (j & 15) * 64, slot = j % 3;
        const bf16* Ap = sgA[seg];
        const bf16* Bp = sgB[seg];
        const uint32_t sa = tbase + slot * STAGE_BYTES, sb = sa + 32768;
#pragma unroll
        for (int u = 0; u < 8; u++) {            // A: 256 rows x 64 cols
            int s = tid + 256 * u, row = s >> 3, cs = s & 7;
            uint32_t so = swz((uint32_t)(row * 128 + cs * 16));
            cp16(sa + so, Ap + (size_t)(m0 + row) * 1024 + k0 + cs * 8);
        }
#pragma unroll
        for (int u = 0; u < 4; u++) {            // B: 128 rows x 64 cols
            int s = tid + 256 * u, row = s >> 3, cs = s & 7;
            uint32_t so = swz((uint32_t)(row * 128 + cs * 16));
            cp16(sb + so, Bp + (size_t)(n0 + row) * 1024 + k0 + cs * 8);
        }
        asm volatile("cp.async.commit_group;" ::: "memory");
    };

    load_chunk(0);
    load_chunk(1);

    uint32_t af[2][4][4], bfr[2][4][4];

    for (int i = 0; i < 48; i++) {
        if (i == 47) asm volatile("cp.async.wait_group 0;" ::: "memory");
        else         asm volatile("cp.async.wait_group 1;" ::: "memory");
        __syncthreads();
        if (i + 2 < 48) load_chunk(i + 2);

        const uint32_t sa = tbase + (i % 3) * STAGE_BYTES, sb = sa + 32768;
        ldfr(af[0], bfr[0], sa, sb, 0, wm, wn, r8, sg);
#pragma unroll
        for (int ks = 0; ks < 4; ks++) {
            const int cur = ks & 1;
            if (ks < 3) ldfr(af[cur ^ 1], bfr[cur ^ 1], sa, sb, (ks + 1) * 32, wm, wn, r8, sg);
#pragma unroll
            for (int mt = 0; mt < 4; mt++)
#pragma unroll
                for (int nq = 0; nq < 4; nq++) {
                    mma16816(acc[mt][2*nq],     af[cur][mt], bfr[cur][nq]);
                    mma16816(acc[mt][2*nq + 1], af[cur][mt], bfr[cur][nq] + 2);
                }
        }
    }

#pragma unroll
    for (int mt = 0; mt < 4; mt++)
#pragma unroll
        for (int ri = 0; ri < 2; ri++) {
            const long long rg = m0 + wm + mt * 16 + ri * 8 + (lane >> 2);
            const float* accp = g.AccC ? g.AccC + (long long)zb * g.sAcc + rg * 1024 : nullptr;
            float* cf = g.wf32 ? g.Cf + (long long)zb * g.sCf + rg * (long long)g.ldcf : nullptr;
            bf16 *chi = nullptr, *clo = nullptr;
            long long bb = 0, tb = 0;
            if (g.wsplit) {
                if (g.trans) { bb = (rg >> 10) * 1048576LL; tb = rg & 1023LL; }
                else         { chi = g.Chi + rg * 1024LL; clo = g.Clo + rg * 1024LL; }
            }
#pragma unroll
            for (int nt = 0; nt < 8; nt++) {
                const int c = n0 + wn + nt * 8 + (lane & 3) * 2;
                float v0 = acc[mt][nt][ri * 2];
                float v1 = acc[mt][nt][ri * 2 + 1];
                if (accp) { float2 tv = *(const float2*)(accp + c); v0 += tv.x; v1 += tv.y; }
                if (g.relu) {
                    v0 = fmaxf(v0 + g.bias[c], 0.f);
                    v1 = fmaxf(v1 + g.bias[c + 1], 0.f);
                }
                if (cf) *(float2*)(cf + c) = make_float2(v0, v1);
                if (g.wsplit) {
                    bf16 h0 = __float2bfloat16(v0), h1 = __float2bfloat16(v1);
                    bf16 l0 = __float2bfloat16(v0 - __bfloat162float(h0));
                    bf16 l1 = __float2bfloat16(v1 - __bfloat162float(h1));
                    if (g.trans) {
                        g.Chi[bb + (long long)c * 1024 + tb] = h0;
                        g.Chi[bb + (long long)(c + 1) * 1024 + tb] = h1;
                        g.Clo[bb + (long long)c * 1024 + tb] = l0;
                        g.Clo[bb + (long long)(c + 1) * 1024 + tb] = l1;
                    } else {
                        *(uint32_t*)(chi + c) = pk(h0, h1);
                        *(uint32_t*)(clo + c) = pk(l0, l1);
                    }
                }
            }
        }
}

__device__ __forceinline__ void split4(float4 v, uint2& h, uint2& l)
{
    bf16 h0=__float2bfloat16(v.x), h1=__float2bfloat16(v.y), h2=__float2bfloat16(v.z), h3=__float2bfloat16(v.w);
    bf16 l0=__float2bfloat16(v.x-__bfloat162float(h0)), l1=__float2bfloat16(v.y-__bfloat162float(h1));
    bf16 l2=__float2bfloat16(v.z-__bfloat162float(h2)), l3=__float2bfloat16(v.w-__bfloat162float(h3));
    h = make_uint2(pk(h0,h1), pk(h2,h3));
    l = make_uint2(pk(l0,l1), pk(l2,l3));
}

__global__ void cvt_in_k(const float* f0, const float* f1, const float* f2, bf16* base)
{
    const float* src = (blockIdx.y == 0) ? f0 : (blockIdx.y == 1) ? f1 : f2;
    size_t i = (size_t)blockIdx.x * 256 + threadIdx.x;
    uint2 h, l;
    split4(((const float4*)src)[i], h, l);
    ((uint2*)(base + 2ULL*blockIdx.y*BIG))[i] = h;
    ((uint2*)(base + (2ULL*blockIdx.y + 1)*BIG))[i] = l;
}

struct WPtrs { const float* p[12]; };
__global__ void cvt_w_k(WPtrs w, bf16* wb)
{
    size_t i = (size_t)blockIdx.x * 256 + threadIdx.x;
    uint2 h, l;
    split4(((const float4*)w.p[blockIdx.y])[i], h, l);
    ((uint2*)(wb + 2ULL*blockIdx.y*MB1))[i] = h;
    ((uint2*)(wb + (2ULL*blockIdx.y + 1)*MB1))[i] = l;
}

__global__ void add_split_k(const float* __restrict__ a, const float* __restrict__ b,
                            bf16* __restrict__ hi, bf16* __restrict__ lo)
{
    size_t i = (size_t)blockIdx.x * 256 + threadIdx.x;
    float4 x = ((const float4*)a)[i];
    float4 y = ((const float4*)b)[i];
    x.x += y.x; x.y += y.y; x.z += y.z; x.w += y.w;
    uint2 h, l;
    split4(x, h, l);
    ((uint2*)hi)[i] = h;
    ((uint2*)lo)[i] = l;
}

// softmax over rows of 1024; grid.x = 3*8192; modality = blockIdx.x >> 13
__global__ void softmax3_k(const float* __restrict__ S, bf16* __restrict__ P)
{
    __shared__ float red[256];
    const int m = blockIdx.x >> 13;
    const size_t row = blockIdx.x & 8191;
    const float* p = S + (size_t)m * BIG + row * 1024;
    int tid = threadIdx.x;
    float4 v = ((const float4*)p)[tid];
    float mx = fmaxf(fmaxf(v.x, v.y), fmaxf(v.z, v.w));
    red[tid] = mx; __syncthreads();
    for (int s = 128; s > 0; s >>= 1) { if (tid < s) red[tid] = fmaxf(red[tid], red[tid+s]); __syncthreads(); }
    mx = red[0]; __syncthreads();
    v.x = __expf(v.x-mx); v.y = __expf(v.y-mx); v.z = __expf(v.z-mx); v.w = __expf(v.w-mx);
    red[tid] = v.x + v.y + v.z + v.w; __syncthreads();
    for (int s = 128; s > 0; s >>= 1) { if (tid < s) red[tid] += red[tid+s]; __syncthreads(); }
    float inv = 1.f / red[0];
    v.x *= inv; v.y *= inv; v.z *= inv; v.w *= inv;
    uint2 h, l;
    split4(v, h, l);
    size_t o = row * 256 + tid;
    ((uint2*)(P + 2ULL*m*BIG))[o] = h;
    ((uint2*)(P + (2ULL*m + 1)*BIG))[o] = l;
}

extern "C" void kernel_launch(void* const* d_in, const int* in_sizes, int n_in,
                              void* d_out, int out_size)
{
    const float* f[3]  = { (const float*)d_in[0], (const float*)d_in[1], (const float*)d_in[2] };
    const float* W[12]; for (int j = 0; j < 12; j++) W[j] = (const float*)d_in[3 + j];
    const float* bp[3] = { (const float*)d_in[15], (const float*)d_in[16], (const float*)d_in[17] };
    float* out = (float*)d_out;

    bf16* BF = nullptr;  cudaGetSymbolAddress((void**)&BF, g_bf);
    float* F32 = nullptr; cudaGetSymbolAddress((void**)&F32, g_f);

    bf16 *FIN = BF, *FP = BF + 6*BIG, *Q = BF + 12*BIG, *Kb = BF + 18*BIG, *VT = BF + 24*BIG;
    bf16 *QS1h = BF + 30*BIG, *QS1l = BF + 31*BIG, *P = BF + 32*BIG, *Wb = BF + 38*BIG;
    float *S = F32, *T = F32 + 3*BIG, *Qf2 = F32 + 4*BIG, *Qf3 = F32 + 5*BIG;
#define PH_(b,i) ((b) + 2ULL*(i)*BIG)
#define PL_(b,i) ((b) + (2ULL*(i)+1)*BIG)
#define WH_(j) (Wb + 2ULL*(j)*MB1)
#define WL_(j) (Wb + (2ULL*(j)+1)*MB1)

    cudaFuncSetAttribute(gemm_b, cudaFuncAttributeMaxDynamicSharedMemorySize, SMEM_ALLOC);

    cvt_in_k<<<dim3(8192,3), 256>>>(f[0], f[1], f[2], BF);
    WPtrs wp; for (int j = 0; j < 12; j++) wp.p[j] = W[j];
    cvt_w_k<<<dim3(1024,12), 256>>>(wp, Wb);

    // 1) preprocess: fp_i = relu(f_i Wp_i^T + b_i) -> out + split
    {
        GTable t = {}; t.nb = 1;
        for (int i = 0; i < 3; i++) {
            GDesc& d = t.d[i];
            d.Ah = PH_(FIN,i); d.Al = PL_(FIN,i); d.Bh = WH_(i); d.Bl = WL_(i);
            d.bias = bp[i]; d.relu = 1;
            d.wf32 = 1; d.Cf = out + 3072 + i*1024; d.ldcf = 6144; d.sCf = 0;
            d.wsplit = 1; d.Chi = PH_(FP,i); d.Clo = PL_(FP,i);
        }
        gemm_b<<<dim3(8,32,3), 256, SMEM_ALLOC>>>(t);
    }
    // 2) QKV projections; Q2/Q3 also fp32; V transposed
    {
        GTable t = {}; t.nb = 1;
        for (int i = 0; i < 3; i++) {
            GDesc* d = &t.d[3*i];
            d[0].Ah = d[1].Ah = d[2].Ah = PH_(FP,i);
            d[0].Al = d[1].Al = d[2].Al = PL_(FP,i);
            d[0].Bh = WH_(3+3*i); d[0].Bl = WL_(3+3*i);
            d[1].Bh = WH_(4+3*i); d[1].Bl = WL_(4+3*i);
            d[2].Bh = WH_(5+3*i); d[2].Bl = WL_(5+3*i);
            d[0].wsplit = 1; d[0].Chi = PH_(Q,i);  d[0].Clo = PL_(Q,i);
            d[1].wsplit = 1; d[1].Chi = PH_(Kb,i); d[1].Clo = PL_(Kb,i);
            d[2].wsplit = 1; d[2].Chi = PH_(VT,i); d[2].Clo = PL_(VT,i); d[2].trans = 1;
            if (i == 1) { d[0].wf32 = 1; d[0].Cf = Qf2; d[0].ldcf = 1024; }
            if (i == 2) { d[0].wf32 = 1; d[0].Cf = Qf3; d[0].ldcf = 1024; }
        }
        gemm_b<<<dim3(8,32,9), 256, SMEM_ALLOC>>>(t);
    }
    // 3) qs1 = q2 + q3 (fp32) -> split
    add_split_k<<<8192, 256>>>(Qf2, Qf3, QS1h, QS1l);

    // 4) T = q1 . k3^T (fp32)
    {
        GTable t = {}; t.nb = 8;
        GDesc& d = t.d[0];
        d.Ah = PH_(Q,0); d.Al = PL_(Q,0); d.Bh = PH_(Kb,2); d.Bl = PL_(Kb,2);
        d.sA = 1048576; d.sB = 1048576;
        d.wf32 = 1; d.Cf = T; d.ldcf = 1024; d.sCf = 1048576;
        gemm_b<<<dim3(8,4,8), 256, SMEM_ALLOC>>>(t);
    }
    // 5) scores: s1 = qs1.k1 ; s2 = T + q3.k2 ; s3 = T + q2.k3
    {
        GTable t = {}; t.nb = 8;
        const bf16* ah[3] = { QS1h, PH_(Q,2), PH_(Q,1) };
        const bf16* al[3] = { QS1l, PL_(Q,2), PL_(Q,1) };
        const int ki[3] = { 0, 1, 2 };
        for (int m = 0; m < 3; m++) {
            GDesc& d = t.d[m];
            d.Ah = ah[m]; d.Al = al[m]; d.Bh = PH_(Kb,ki[m]); d.Bl = PL_(Kb,ki[m]);
            d.sA = 1048576; d.sB = 1048576;
            if (m > 0) { d.AccC = T; d.sAcc = 1048576; }
            d.wf32 = 1; d.Cf = S + (size_t)m*BIG; d.ldcf = 1024; d.sCf = 1048576;
        }
        gemm_b<<<dim3(8,4,24), 256, SMEM_ALLOC>>>(t);
    }
    // 6) softmax + split P for all 3 modalities
    softmax3_k<<<24576, 256>>>(S, P);

    // 7) AV: f_mu = P_m @ V_m -> out cols [m*1024, (m+1)*1024)
    {
        GTable t = {}; t.nb = 8;
        for (int m = 0; m < 3; m++) {
            GDesc& d = t.d[m];
            d.Ah = PH_(P,m); d.Al = PL_(P,m); d.Bh = PH_(VT,m); d.Bl = PL_(VT,m);
            d.sA = 1048576; d.sB = 1048576;
            d.wf32 = 1; d.Cf = out + m*1024; d.ldcf = 6144; d.sCf = (long long)1024*6144;
        }
        gemm_b<<<dim3(8,4,24), 256, SMEM_ALLOC>>>(t);
    }
}

// round 9
// speedup vs baseline: 1.8668x; 1.8668x over previous
#include <cuda_runtime.h>
#include <cuda_bf16.h>
#include <cstdint>

typedef __nv_bfloat16 bf16;

#define STAGE_BYTES 49152               // A 16K + Bh 16K + Bl 16K
#define SMEM_ALLOC (1024 + 2*STAGE_BYTES)

#define BIG 8388608ULL
#define MB1 1048576ULL

// bf16 arena: FIN 0-6, FP 6-12, Q 12-18, K 18-24, VT 24-30, QS1 30-32, P 32-38, W 38..+24MB1
__device__ bf16  g_bf[38ULL*BIG + 24ULL*MB1];
// f32 arena: S 0-3, T 3-4, Qf2 4-5, Qf3 5-6
__device__ float g_f[6ULL*BIG];

__device__ __forceinline__ uint32_t su32(const void* p){ return (uint32_t)__cvta_generic_to_shared(p); }
__device__ __forceinline__ void cp16(uint32_t s, const void* g){
    asm volatile("cp.async.cg.shared.global [%0], [%1], 16;"
        :: "r"(s), "l"((unsigned long long)__cvta_generic_to_global(g)) : "memory");
}
__device__ __forceinline__ uint32_t pk(bf16 a, bf16 b){
    return (uint32_t)__bfloat16_as_ushort(a) | ((uint32_t)__bfloat16_as_ushort(b) << 16);
}
__device__ __forceinline__ uint32_t swz(uint32_t o){ return o ^ ((o >> 3) & 0x70); }

__device__ __forceinline__ void ldsm4(uint32_t* r, uint32_t addr){
    asm volatile("ldmatrix.sync.aligned.m8n8.x4.shared.b16 {%0,%1,%2,%3}, [%4];"
        : "=r"(r[0]), "=r"(r[1]), "=r"(r[2]), "=r"(r[3]) : "r"(addr));
}
__device__ __forceinline__ void mma16816(float* d, const uint32_t* a, const uint32_t* b){
    asm volatile("mma.sync.aligned.m16n8k16.row.col.f32.bf16.bf16.f32 "
        "{%0,%1,%2,%3}, {%4,%5,%6,%7}, {%8,%9}, {%0,%1,%2,%3};"
        : "+f"(d[0]), "+f"(d[1]), "+f"(d[2]), "+f"(d[3])
        : "r"(a[0]), "r"(a[1]), "r"(a[2]), "r"(a[3]), "r"(b[0]), "r"(b[1]));
}

struct GDesc {
    const bf16 *Ah, *Al, *Bh, *Bl;
    long long sA, sB;
    const float* bias;
    const float* AccC; long long sAcc;
    float* Cf; long long sCf; int ldcf;
    bf16 *Chi, *Clo;
    int trans, relu, wf32, wsplit;
};
struct GTable { GDesc d[9]; int nb; };

__device__ __forceinline__ void ldfrA(uint32_t (*afb)[4], uint32_t sa, int kb,
                                      int wm, int r8, int sg)
{
#pragma unroll
    for (int mt = 0; mt < 4; mt++) {
        int row = wm + mt*16 + r8 + ((sg & 1) << 3);
        ldsm4(afb[mt], sa + swz((uint32_t)(row*128 + kb + ((sg >> 1) << 4))));
    }
}
__device__ __forceinline__ void ldfrB(uint32_t (*bfb)[4], uint32_t sb, int kb,
                                      int wn, int r8, int sg)
{
#pragma unroll
    for (int nq = 0; nq < 4; nq++) {
        int row = wn + nq*16 + r8 + ((sg >> 1) << 3);
        ldsm4(bfb[nq], sb + swz((uint32_t)(row*128 + kb + ((sg & 1) << 4))));
    }
}

// batched 3-term split GEMM: C = Ah Bh^T + Al Bh^T + Ah Bl^T (+AccC) (+bias,relu)
// 128 threads, 4 warps, warp tile 64x64; per-k chunk types:
//   even chunk (type1): {Ah, Bh, Bl} -> Ah*Bh + Ah*Bl
//   odd  chunk (type2): {Al, Bh}     -> Al*Bh
__global__ void __launch_bounds__(128, 2) gemm_b(GTable t)
{
    extern __shared__ char smem[];
    const uint32_t tbase = (su32(smem) + 1023u) & ~1023u;
    const int tid = threadIdx.x, wid = tid >> 5, lane = tid & 31;
    const int di = blockIdx.z / t.nb, zb = blockIdx.z - di * t.nb;
    const GDesc g = t.d[di];
    const int m0 = blockIdx.y * 128, n0 = blockIdx.x * 128;
    const int wm = (wid & 1) * 64, wn = (wid >> 1) * 64;
    const int r8 = lane & 7, sg = lane >> 3;

    const bf16* Ah = g.Ah + (long long)zb * g.sA;
    const bf16* Al = g.Al + (long long)zb * g.sA;
    const bf16* Bh = g.Bh + (long long)zb * g.sB;
    const bf16* Bl = g.Bl + (long long)zb * g.sB;

    float acc[4][8][4];
#pragma unroll
    for (int a = 0; a < 4; a++)
#pragma unroll
        for (int b = 0; b < 8; b++)
#pragma unroll
            for (int c = 0; c < 4; c++) acc[a][b][c] = 0.f;

    // chunk j (0..31): k-group = j>>1, type = j&1, slot = j&1
    auto load_chunk = [&](int j) {
        const int k0 = (j >> 1) * 64;
        const uint32_t sa = tbase + (uint32_t)(j & 1) * STAGE_BYTES;
        if ((j & 1) == 0) {
#pragma unroll
            for (int u = 0; u < 8; u++) {
                int s = tid + 128 * u, row = s >> 3, cs = s & 7;
                uint32_t so = swz((uint32_t)(row * 128 + cs * 16));
                const size_t go = (size_t)row * 1024 + k0 + cs * 8;
                cp16(sa + so,         Ah + (size_t)m0 * 1024 + go);
                cp16(sa + 16384 + so, Bh + (size_t)n0 * 1024 + go);
                cp16(sa + 32768 + so, Bl + (size_t)n0 * 1024 + go);
            }
        } else {
#pragma unroll
            for (int u = 0; u < 8; u++) {
                int s = tid + 128 * u, row = s >> 3, cs = s & 7;
                uint32_t so = swz((uint32_t)(row * 128 + cs * 16));
                const size_t go = (size_t)row * 1024 + k0 + cs * 8;
                cp16(sa + so,         Al + (size_t)m0 * 1024 + go);
                cp16(sa + 16384 + so, Bh + (size_t)n0 * 1024 + go);
            }
        }
        asm volatile("cp.async.commit_group;" ::: "memory");
    };

    load_chunk(0);

    uint32_t af[2][4][4], bfr[2][4][4];

    for (int i = 0; i < 32; i++) {
        asm volatile("cp.async.wait_group 0;" ::: "memory");
        __syncthreads();
        if (i + 1 < 32) load_chunk(i + 1);

        const uint32_t sa  = tbase + (uint32_t)(i & 1) * STAGE_BYTES;
        const uint32_t sbh = sa + 16384, sbl = sa + 32768;

        if ((i & 1) == 0) {
            // type1: 8 micro-iters over (ks, Bh/Bl)
            ldfrA(af[0], sa, 0, wm, r8, sg);
            ldfrB(bfr[0], sbh, 0, wn, r8, sg);
#pragma unroll
            for (int it = 0; it < 8; it++) {
                const int cur = it & 1;
                const int ks = it >> 1;
                if (it < 7) {
                    const int nit = it + 1, nks = nit >> 1;
                    ldfrB(bfr[cur ^ 1], (nit & 1) ? sbl : sbh, nks * 32, wn, r8, sg);
                    if ((nit & 1) == 0) ldfrA(af[nks & 1], sa, nks * 32, wm, r8, sg);
                }
                const uint32_t (*am)[4] = af[ks & 1];
#pragma unroll
                for (int mt = 0; mt < 4; mt++)
#pragma unroll
                    for (int nq = 0; nq < 4; nq++) {
                        mma16816(acc[mt][2*nq],     am[mt], bfr[cur][nq]);
                        mma16816(acc[mt][2*nq + 1], am[mt], bfr[cur][nq] + 2);
                    }
            }
        } else {
            // type2: standard 4 k-steps
            ldfrA(af[0], sa, 0, wm, r8, sg);
            ldfrB(bfr[0], sbh, 0, wn, r8, sg);
#pragma unroll
            for (int ks = 0; ks < 4; ks++) {
                const int cur = ks & 1;
                if (ks < 3) {
                    ldfrA(af[cur ^ 1], sa, (ks + 1) * 32, wm, r8, sg);
                    ldfrB(bfr[cur ^ 1], sbh, (ks + 1) * 32, wn, r8, sg);
                }
#pragma unroll
                for (int mt = 0; mt < 4; mt++)
#pragma unroll
                    for (int nq = 0; nq < 4; nq++) {
                        mma16816(acc[mt][2*nq],     af[cur][mt], bfr[cur][nq]);
                        mma16816(acc[mt][2*nq + 1], af[cur][mt], bfr[cur][nq] + 2);
                    }
            }
        }
    }

#pragma unroll
    for (int mt = 0; mt < 4; mt++)
#pragma unroll
        for (int ri = 0; ri < 2; ri++) {
            const long long rg = m0 + wm + mt * 16 + ri * 8 + (lane >> 2);
            const float* accp = g.AccC ? g.AccC + (long long)zb * g.sAcc + rg * 1024 : nullptr;
            float* cf = g.wf32 ? g.Cf + (long long)zb * g.sCf + rg * (long long)g.ldcf : nullptr;
            bf16 *chi = nullptr, *clo = nullptr;
            long long bb = 0, tb = 0;
            if (g.wsplit) {
                if (g.trans) { bb = (rg >> 10) * 1048576LL; tb = rg & 1023LL; }
                else         { chi = g.Chi + rg * 1024LL; clo = g.Clo + rg * 1024LL; }
            }
#pragma unroll
            for (int nt = 0; nt < 8; nt++) {
                const int c = n0 + wn + nt * 8 + (lane & 3) * 2;
                float v0 = acc[mt][nt][ri * 2];
                float v1 = acc[mt][nt][ri * 2 + 1];
                if (accp) { float2 tv = *(const float2*)(accp + c); v0 += tv.x; v1 += tv.y; }
                if (g.relu) {
                    v0 = fmaxf(v0 + g.bias[c], 0.f);
                    v1 = fmaxf(v1 + g.bias[c + 1], 0.f);
                }
                if (cf) *(float2*)(cf + c) = make_float2(v0, v1);
                if (g.wsplit) {
                    bf16 h0 = __float2bfloat16(v0), h1 = __float2bfloat16(v1);
                    bf16 l0 = __float2bfloat16(v0 - __bfloat162float(h0));
                    bf16 l1 = __float2bfloat16(v1 - __bfloat162float(h1));
                    if (g.trans) {
                        g.Chi[bb + (long long)c * 1024 + tb] = h0;
                        g.Chi[bb + (long long)(c + 1) * 1024 + tb] = h1;
                        g.Clo[bb + (long long)c * 1024 + tb] = l0;
                        g.Clo[bb + (long long)(c + 1) * 1024 + tb] = l1;
                    } else {
                        *(uint32_t*)(chi + c) = pk(h0, h1);
                        *(uint32_t*)(clo + c) = pk(l0, l1);
                    }
                }
            }
        }
}

__device__ __forceinline__ void split4(float4 v, uint2& h, uint2& l)
{
    bf16 h0=__float2bfloat16(v.x), h1=__float2bfloat16(v.y), h2=__float2bfloat16(v.z), h3=__float2bfloat16(v.w);
    bf16 l0=__float2bfloat16(v.x-__bfloat162float(h0)), l1=__float2bfloat16(v.y-__bfloat162float(h1));
    bf16 l2=__float2bfloat16(v.z-__bfloat162float(h2)), l3=__float2bfloat16(v.w-__bfloat162float(h3));
    h = make_uint2(pk(h0,h1), pk(h2,h3));
    l = make_uint2(pk(l0,l1), pk(l2,l3));
}

__global__ void cvt_in_k(const float* f0, const float* f1, const float* f2, bf16* base)
{
    const float* src = (blockIdx.y == 0) ? f0 : (blockIdx.y == 1) ? f1 : f2;
    size_t i = (size_t)blockIdx.x * 256 + threadIdx.x;
    uint2 h, l;
    split4(((const float4*)src)[i], h, l);
    ((uint2*)(base + 2ULL*blockIdx.y*BIG))[i] = h;
    ((uint2*)(base + (2ULL*blockIdx.y + 1)*BIG))[i] = l;
}

struct WPtrs { const float* p[12]; };
__global__ void cvt_w_k(WPtrs w, bf16* wb)
{
    size_t i = (size_t)blockIdx.x * 256 + threadIdx.x;
    uint2 h, l;
    split4(((const float4*)w.p[blockIdx.y])[i], h, l);
    ((uint2*)(wb + 2ULL*blockIdx.y*MB1))[i] = h;
    ((uint2*)(wb + (2ULL*blockIdx.y + 1)*MB1))[i] = l;
}

__global__ void add_split_k(const float* __restrict__ a, const float* __restrict__ b,
                            bf16* __restrict__ hi, bf16* __restrict__ lo)
{
    size_t i = (size_t)blockIdx.x * 256 + threadIdx.x;
    float4 x = ((const float4*)a)[i];
    float4 y = ((const float4*)b)[i];
    x.x += y.x; x.y += y.y; x.z += y.z; x.w += y.w;
    uint2 h, l;
    split4(x, h, l);
    ((uint2*)hi)[i] = h;
    ((uint2*)lo)[i] = l;
}

// softmax over rows of 1024; grid.x = 3*8192; modality = blockIdx.x >> 13
__global__ void softmax3_k(const float* __restrict__ S, bf16* __restrict__ P)
{
    __shared__ float red[256];
    const int m = blockIdx.x >> 13;
    const size_t row = blockIdx.x & 8191;
    const float* p = S + (size_t)m * BIG + row * 1024;
    int tid = threadIdx.x;
    float4 v = ((const float4*)p)[tid];
    float mx = fmaxf(fmaxf(v.x, v.y), fmaxf(v.z, v.w));
    red[tid] = mx; __syncthreads();
    for (int s = 128; s > 0; s >>= 1) { if (tid < s) red[tid] = fmaxf(red[tid], red[tid+s]); __syncthreads(); }
    mx = red[0]; __syncthreads();
    v.x = __expf(v.x-mx); v.y = __expf(v.y-mx); v.z = __expf(v.z-mx); v.w = __expf(v.w-mx);
    red[tid] = v.x + v.y + v.z + v.w; __syncthreads();
    for (int s = 128; s > 0; s >>= 1) { if (tid < s) red[tid] += red[tid+s]; __syncthreads(); }
    float inv = 1.f / red[0];
    v.x *= inv; v.y *= inv; v.z *= inv; v.w *= inv;
    uint2 h, l;
    split4(v, h, l);
    size_t o = row * 256 + tid;
    ((uint2*)(P + 2ULL*m*BIG))[o] = h;
    ((uint2*)(P + (2ULL*m + 1)*BIG))[o] = l;
}

extern "C" void kernel_launch(void* const* d_in, const int* in_sizes, int n_in,
                              void* d_out, int out_size)
{
    const float* f[3]  = { (const float*)d_in[0], (const float*)d_in[1], (const float*)d_in[2] };
    const float* W[12]; for (int j = 0; j < 12; j++) W[j] = (const float*)d_in[3 + j];
    const float* bp[3] = { (const float*)d_in[15], (const float*)d_in[16], (const float*)d_in[17] };
    float* out = (float*)d_out;

    bf16* BF = nullptr;  cudaGetSymbolAddress((void**)&BF, g_bf);
    float* F32 = nullptr; cudaGetSymbolAddress((void**)&F32, g_f);

    bf16 *FIN = BF, *FP = BF + 6*BIG, *Q = BF + 12*BIG, *Kb = BF + 18*BIG, *VT = BF + 24*BIG;
    bf16 *QS1h = BF + 30*BIG, *QS1l = BF + 31*BIG, *P = BF + 32*BIG, *Wb = BF + 38*BIG;
    float *S = F32, *T = F32 + 3*BIG, *Qf2 = F32 + 4*BIG, *Qf3 = F32 + 5*BIG;
#define PH_(b,i) ((b) + 2ULL*(i)*BIG)
#define PL_(b,i) ((b) + (2ULL*(i)+1)*BIG)
#define WH_(j) (Wb + 2ULL*(j)*MB1)
#define WL_(j) (Wb + (2ULL*(j)+1)*MB1)

    cudaFuncSetAttribute(gemm_b, cudaFuncAttributeMaxDynamicSharedMemorySize, SMEM_ALLOC);

    cvt_in_k<<<dim3(8192,3), 256>>>(f[0], f[1], f[2], BF);
    WPtrs wp; for (int j = 0; j < 12; j++) wp.p[j] = W[j];
    cvt_w_k<<<dim3(1024,12), 256>>>(wp, Wb);

    // 1) preprocess: fp_i = relu(f_i Wp_i^T + b_i) -> out + split
    {
        GTable t = {}; t.nb = 1;
        for (int i = 0; i < 3; i++) {
            GDesc& d = t.d[i];
            d.Ah = PH_(FIN,i); d.Al = PL_(FIN,i); d.Bh = WH_(i); d.Bl = WL_(i);
            d.bias = bp[i]; d.relu = 1;
            d.wf32 = 1; d.Cf = out + 3072 + i*1024; d.ldcf = 6144; d.sCf = 0;
            d.wsplit = 1; d.Chi = PH_(FP,i); d.Clo = PL_(FP,i);
        }
        gemm_b<<<dim3(8,64,3), 128, SMEM_ALLOC>>>(t);
    }
    // 2) QKV projections; Q2/Q3 also fp32; V transposed
    {
        GTable t = {}; t.nb = 1;
        for (int i = 0; i < 3; i++) {
            GDesc* d = &t.d[3*i];
            d[0].Ah = d[1].Ah = d[2].Ah = PH_(FP,i);
            d[0].Al = d[1].Al = d[2].Al = PL_(FP,i);
            d[0].Bh = WH_(3+3*i); d[0].Bl = WL_(3+3*i);
            d[1].Bh = WH_(4+3*i); d[1].Bl = WL_(4+3*i);
            d[2].Bh = WH_(5+3*i); d[2].Bl = WL_(5+3*i);
            d[0].wsplit = 1; d[0].Chi = PH_(Q,i);  d[0].Clo = PL_(Q,i);
            d[1].wsplit = 1; d[1].Chi = PH_(Kb,i); d[1].Clo = PL_(Kb,i);
            d[2].wsplit = 1; d[2].Chi = PH_(VT,i); d[2].Clo = PL_(VT,i); d[2].trans = 1;
            if (i == 1) { d[0].wf32 = 1; d[0].Cf = Qf2; d[0].ldcf = 1024; }
            if (i == 2) { d[0].wf32 = 1; d[0].Cf = Qf3; d[0].ldcf = 1024; }
        }
        gemm_b<<<dim3(8,64,9), 128, SMEM_ALLOC>>>(t);
    }
    // 3) qs1 = q2 + q3 (fp32) -> split
    add_split_k<<<8192, 256>>>(Qf2, Qf3, QS1h, QS1l);

    // 4) T = q1 . k3^T (fp32)
    {
        GTable t = {}; t.nb = 8;
        GDesc& d = t.d[0];
        d.Ah = PH_(Q,0); d.Al = PL_(Q,0); d.Bh = PH_(Kb,2); d.Bl = PL_(Kb,2);
        d.sA = 1048576; d.sB = 1048576;
        d.wf32 = 1; d.Cf = T; d.ldcf = 1024; d.sCf = 1048576;
        gemm_b<<<dim3(8,8,8), 128, SMEM_ALLOC>>>(t);
    }
    // 5) scores: s1 = qs1.k1 ; s2 = T + q3.k2 ; s3 = T + q2.k3
    {
        GTable t = {}; t.nb = 8;
        const bf16* ah[3] = { QS1h, PH_(Q,2), PH_(Q,1) };
        const bf16* al[3] = { QS1l, PL_(Q,2), PL_(Q,1) };
        const int ki[3] = { 0, 1, 2 };
        for (int m = 0; m < 3; m++) {
            GDesc& d = t.d[m];
            d.Ah = ah[m]; d.Al = al[m]; d.Bh = PH_(Kb,ki[m]); d.Bl = PL_(Kb,ki[m]);
            d.sA = 1048576; d.sB = 1048576;
            if (m > 0) { d.AccC = T; d.sAcc = 1048576; }
            d.wf32 = 1; d.Cf = S + (size_t)m*BIG; d.ldcf = 1024; d.sCf = 1048576;
        }
        gemm_b<<<dim3(8,8,24), 128, SMEM_ALLOC>>>(t);
    }
    // 6) softmax + split P for all 3 modalities
    softmax3_k<<<24576, 256>>>(S, P);

    // 7) AV: f_mu = P_m @ V_m -> out cols [m*1024, (m+1)*1024)
    {
        GTable t = {}; t.nb = 8;
        for (int m = 0; m < 3; m++) {
            GDesc& d = t.d[m];
            d.Ah = PH_(P,m); d.Al = PL_(P,m); d.Bh = PH_(VT,m); d.Bl = PL_(VT,m);
            d.sA = 1048576; d.sB = 1048576;
            d.wf32 = 1; d.Cf = out + m*1024; d.ldcf = 6144; d.sCf = (long long)1024*6144;
        }
        gemm_b<<<dim3(8,8,24), 128, SMEM_ALLOC>>>(t);
    }
}

// round 10
// speedup vs baseline: 2.7185x; 1.4562x over previous
#include <cuda_runtime.h>
#include <cuda_fp16.h>
#include <cstdint>

typedef __half fp16;

#define STAGE_BYTES 49152               // Ah 16K + Al 16K + B 16K
#define SMEM_ALLOC (1024 + 2*STAGE_BYTES)

#define BIG 8388608ULL
#define MB1 1048576ULL

// fp16 arena: FIN 0-6 (hi/lo x3), FP 6-12, Q 12-18, K 18-21 (hi only),
//             VT 21-24 (hi only), QS1 24-26, P 26-32, W 32..+12MB1 (hi only)
__device__ fp16  g_hf[32ULL*BIG + 12ULL*MB1];
// f32 arena: S 0-3, T 3-4, Qf2 4-5, Qf3 5-6
__device__ float g_f[6ULL*BIG];

__device__ __forceinline__ uint32_t su32(const void* p){ return (uint32_t)__cvta_generic_to_shared(p); }
__device__ __forceinline__ void cp16(uint32_t s, const void* g){
    asm volatile("cp.async.cg.shared.global [%0], [%1], 16;"
        :: "r"(s), "l"((unsigned long long)__cvta_generic_to_global(g)) : "memory");
}
__device__ __forceinline__ uint32_t pk(fp16 a, fp16 b){
    return (uint32_t)__half_as_ushort(a) | ((uint32_t)__half_as_ushort(b) << 16);
}
__device__ __forceinline__ uint32_t swz(uint32_t o){ return o ^ ((o >> 3) & 0x70); }

__device__ __forceinline__ void ldsm4(uint32_t* r, uint32_t addr){
    asm volatile("ldmatrix.sync.aligned.m8n8.x4.shared.b16 {%0,%1,%2,%3}, [%4];"
        : "=r"(r[0]), "=r"(r[1]), "=r"(r[2]), "=r"(r[3]) : "r"(addr));
}
__device__ __forceinline__ void mma16816(float* d, const uint32_t* a, const uint32_t* b){
    asm volatile("mma.sync.aligned.m16n8k16.row.col.f32.f16.f16.f32 "
        "{%0,%1,%2,%3}, {%4,%5,%6,%7}, {%8,%9}, {%0,%1,%2,%3};"
        : "+f"(d[0]), "+f"(d[1]), "+f"(d[2]), "+f"(d[3])
        : "r"(a[0]), "r"(a[1]), "r"(a[2]), "r"(a[3]), "r"(b[0]), "r"(b[1]));
}

struct GDesc {
    const fp16 *Ah, *Al, *Bh;
    long long sA, sB;
    const float* bias;
    const float* AccC; long long sAcc;
    float* Cf; long long sCf; int ldcf;
    fp16 *Chi, *Clo;                    // Clo==nullptr -> hi plane only
    int trans, relu, wf32, wsplit;
};
struct GTable { GDesc d[9]; int nb; };

__device__ __forceinline__ void ldfrA(uint32_t (*afb)[4], uint32_t sa, int kb,
                                      int wm, int r8, int sg)
{
#pragma unroll
    for (int mt = 0; mt < 4; mt++) {
        int row = wm + mt*16 + r8 + ((sg & 1) << 3);
        ldsm4(afb[mt], sa + swz((uint32_t)(row*128 + kb + ((sg >> 1) << 4))));
    }
}
__device__ __forceinline__ void ldfrB(uint32_t (*bfb)[4], uint32_t sb, int kb,
                                      int wn, int r8, int sg)
{
#pragma unroll
    for (int nq = 0; nq < 4; nq++) {
        int row = wn + nq*16 + r8 + ((sg >> 1) << 3);
        ldsm4(bfb[nq], sb + swz((uint32_t)(row*128 + kb + ((sg & 1) << 4))));
    }
}

// batched 2-term fp16 split GEMM: C = Ah B^T + Al B^T (+AccC) (+bias,relu)
// 128 threads, 4 warps, warp tile 64x64; chunk = {Ah, Al, B} K=64 slab
__global__ void __launch_bounds__(128, 2) gemm_b(GTable t)
{
    extern __shared__ char smem[];
    const uint32_t tbase = (su32(smem) + 1023u) & ~1023u;
    const int tid = threadIdx.x, wid = tid >> 5, lane = tid & 31;
    const int di = blockIdx.z / t.nb, zb = blockIdx.z - di * t.nb;
    const GDesc g = t.d[di];
    const int m0 = blockIdx.y * 128, n0 = blockIdx.x * 128;
    const int wm = (wid & 1) * 64, wn = (wid >> 1) * 64;
    const int r8 = lane & 7, sg = lane >> 3;

    const fp16* Ah = g.Ah + (long long)zb * g.sA;
    const fp16* Al = g.Al + (long long)zb * g.sA;
    const fp16* Bh = g.Bh + (long long)zb * g.sB;

    float acc[4][8][4];
#pragma unroll
    for (int a = 0; a < 4; a++)
#pragma unroll
        for (int b = 0; b < 8; b++)
#pragma unroll
            for (int c = 0; c < 4; c++) acc[a][b][c] = 0.f;

    auto load_chunk = [&](int j) {
        const int k0 = j * 64;
        const uint32_t sa = tbase + (uint32_t)(j & 1) * STAGE_BYTES;
#pragma unroll
        for (int u = 0; u < 8; u++) {
            int s = tid + 128 * u, row = s >> 3, cs = s & 7;
            uint32_t so = swz((uint32_t)(row * 128 + cs * 16));
            const size_t go = (size_t)row * 1024 + k0 + cs * 8;
            cp16(sa + so,         Ah + (size_t)m0 * 1024 + go);
            cp16(sa + 16384 + so, Al + (size_t)m0 * 1024 + go);
            cp16(sa + 32768 + so, Bh + (size_t)n0 * 1024 + go);
        }
        asm volatile("cp.async.commit_group;" ::: "memory");
    };

    load_chunk(0);

    uint32_t af[2][4][4], bfr[2][4][4];

    for (int i = 0; i < 16; i++) {
        asm volatile("cp.async.wait_group 0;" ::: "memory");
        __syncthreads();
        if (i + 1 < 16) load_chunk(i + 1);

        const uint32_t sa  = tbase + (uint32_t)(i & 1) * STAGE_BYTES;
        const uint32_t sal = sa + 16384, sb = sa + 32768;

        // 8 micro-iters: it -> ks = it>>1, A-plane = (it&1) ? lo : hi
        ldfrA(af[0], sa, 0, wm, r8, sg);
        ldfrB(bfr[0], sb, 0, wn, r8, sg);
#pragma unroll
        for (int it = 0; it < 8; it++) {
            const int cur = it & 1;
            const int ks = it >> 1;
            if (it < 7) {
                const int nit = it + 1, nks = nit >> 1;
                ldfrA(af[cur ^ 1], (nit & 1) ? sal : sa, nks * 32, wm, r8, sg);
                if ((nit & 1) == 0) ldfrB(bfr[nks & 1], sb, nks * 32, wn, r8, sg);
            }
            const uint32_t (*bm)[4] = bfr[ks & 1];
#pragma unroll
            for (int mt = 0; mt < 4; mt++)
#pragma unroll
                for (int nq = 0; nq < 4; nq++) {
                    mma16816(acc[mt][2*nq],     af[cur][mt], bm[nq]);
                    mma16816(acc[mt][2*nq + 1], af[cur][mt], bm[nq] + 2);
                }
        }
    }

#pragma unroll
    for (int mt = 0; mt < 4; mt++)
#pragma unroll
        for (int ri = 0; ri < 2; ri++) {
            const long long rg = m0 + wm + mt * 16 + ri * 8 + (lane >> 2);
            const float* accp = g.AccC ? g.AccC + (long long)zb * g.sAcc + rg * 1024 : nullptr;
            float* cf = g.wf32 ? g.Cf + (long long)zb * g.sCf + rg * (long long)g.ldcf : nullptr;
            fp16 *chi = nullptr, *clo = nullptr;
            long long bb = 0, tb = 0;
            if (g.wsplit) {
                if (g.trans) { bb = (rg >> 10) * 1048576LL; tb = rg & 1023LL; }
                else {
                    chi = g.Chi + rg * 1024LL;
                    if (g.Clo) clo = g.Clo + rg * 1024LL;
                }
            }
#pragma unroll
            for (int nt = 0; nt < 8; nt++) {
                const int c = n0 + wn + nt * 8 + (lane & 3) * 2;
                float v0 = acc[mt][nt][ri * 2];
                float v1 = acc[mt][nt][ri * 2 + 1];
                if (accp) { float2 tv = *(const float2*)(accp + c); v0 += tv.x; v1 += tv.y; }
                if (g.relu) {
                    v0 = fmaxf(v0 + g.bias[c], 0.f);
                    v1 = fmaxf(v1 + g.bias[c + 1], 0.f);
                }
                if (cf) *(float2*)(cf + c) = make_float2(v0, v1);
                if (g.wsplit) {
                    fp16 h0 = __float2half_rn(v0), h1 = __float2half_rn(v1);
                    if (g.trans) {
                        g.Chi[bb + (long long)c * 1024 + tb] = h0;
                        g.Chi[bb + (long long)(c + 1) * 1024 + tb] = h1;
                        if (g.Clo) {
                            fp16 l0 = __float2half_rn(v0 - __half2float(h0));
                            fp16 l1 = __float2half_rn(v1 - __half2float(h1));
                            g.Clo[bb + (long long)c * 1024 + tb] = l0;
                            g.Clo[bb + (long long)(c + 1) * 1024 + tb] = l1;
                        }
                    } else {
                        *(uint32_t*)(chi + c) = pk(h0, h1);
                        if (clo) {
                            fp16 l0 = __float2half_rn(v0 - __half2float(h0));
                            fp16 l1 = __float2half_rn(v1 - __half2float(h1));
                            *(uint32_t*)(clo + c) = pk(l0, l1);
                        }
                    }
                }
            }
        }
}

__device__ __forceinline__ void split4(float4 v, uint2& h, uint2& l)
{
    fp16 h0=__float2half_rn(v.x), h1=__float2half_rn(v.y), h2=__float2half_rn(v.z), h3=__float2half_rn(v.w);
    fp16 l0=__float2half_rn(v.x-__half2float(h0)), l1=__float2half_rn(v.y-__half2float(h1));
    fp16 l2=__float2half_rn(v.z-__half2float(h2)), l3=__float2half_rn(v.w-__half2float(h3));
    h = make_uint2(pk(h0,h1), pk(h2,h3));
    l = make_uint2(pk(l0,l1), pk(l2,l3));
}

__global__ void cvt_in_k(const float* f0, const float* f1, const float* f2, fp16* base)
{
    const float* src = (blockIdx.y == 0) ? f0 : (blockIdx.y == 1) ? f1 : f2;
    size_t i = (size_t)blockIdx.x * 256 + threadIdx.x;
    uint2 h, l;
    split4(((const float4*)src)[i], h, l);
    ((uint2*)(base + 2ULL*blockIdx.y*BIG))[i] = h;
    ((uint2*)(base + (2ULL*blockIdx.y + 1)*BIG))[i] = l;
}

struct WPtrs { const float* p[12]; };
__global__ void cvt_w_k(WPtrs w, fp16* wb)   // hi plane only (B-role)
{
    size_t i = (size_t)blockIdx.x * 256 + threadIdx.x;
    float4 v = ((const float4*)w.p[blockIdx.y])[i];
    uint2 h = make_uint2(pk(__float2half_rn(v.x), __float2half_rn(v.y)),
                         pk(__float2half_rn(v.z), __float2half_rn(v.w)));
    ((uint2*)(wb + (size_t)blockIdx.y*MB1))[i] = h;
}

__global__ void add_split_k(const float* __restrict__ a, const float* __restrict__ b,
                            fp16* __restrict__ hi, fp16* __restrict__ lo)
{
    size_t i = (size_t)blockIdx.x * 256 + threadIdx.x;
    float4 x = ((const float4*)a)[i];
    float4 y = ((const float4*)b)[i];
    x.x += y.x; x.y += y.y; x.z += y.z; x.w += y.w;
    uint2 h, l;
    split4(x, h, l);
    ((uint2*)hi)[i] = h;
    ((uint2*)lo)[i] = l;
}

// softmax over rows of 1024; grid.x = 3*8192; modality = blockIdx.x >> 13
__global__ void softmax3_k(const float* __restrict__ S, fp16* __restrict__ P)
{
    __shared__ float red[256];
    const int m = blockIdx.x >> 13;
    const size_t row = blockIdx.x & 8191;
    const float* p = S + (size_t)m * BIG + row * 1024;
    int tid = threadIdx.x;
    float4 v = ((const float4*)p)[tid];
    float mx = fmaxf(fmaxf(v.x, v.y), fmaxf(v.z, v.w));
    red[tid] = mx; __syncthreads();
    for (int s = 128; s > 0; s >>= 1) { if (tid < s) red[tid] = fmaxf(red[tid], red[tid+s]); __syncthreads(); }
    mx = red[0]; __syncthreads();
    v.x = __expf(v.x-mx); v.y = __expf(v.y-mx); v.z = __expf(v.z-mx); v.w = __expf(v.w-mx);
    red[tid] = v.x + v.y + v.z + v.w; __syncthreads();
    for (int s = 128; s > 0; s >>= 1) { if (tid < s) red[tid] += red[tid+s]; __syncthreads(); }
    float inv = 1.f / red[0];
    v.x *= inv; v.y *= inv; v.z *= inv; v.w *= inv;
    uint2 h, l;
    split4(v, h, l);
    size_t o = row * 256 + tid;
    ((uint2*)(P + 2ULL*m*BIG))[o] = h;
    ((uint2*)(P + (2ULL*m + 1)*BIG))[o] = l;
}

extern "C" void kernel_launch(void* const* d_in, const int* in_sizes, int n_in,
                              void* d_out, int out_size)
{
    const float* f[3]  = { (const float*)d_in[0], (const float*)d_in[1], (const float*)d_in[2] };
    const float* W[12]; for (int j = 0; j < 12; j++) W[j] = (const float*)d_in[3 + j];
    const float* bp[3] = { (const float*)d_in[15], (const float*)d_in[16], (const float*)d_in[17] };
    float* out = (float*)d_out;

    fp16* HF = nullptr;  cudaGetSymbolAddress((void**)&HF, g_hf);
    float* F32 = nullptr; cudaGetSymbolAddress((void**)&F32, g_f);

    fp16 *FIN = HF, *FP = HF + 6*BIG, *Q = HF + 12*BIG;
    fp16 *Kb = HF + 18*BIG, *VT = HF + 21*BIG;          // hi-only, 1 slot per modality
    fp16 *QS1h = HF + 24*BIG, *QS1l = HF + 25*BIG, *P = HF + 26*BIG, *Wb = HF + 32*BIG;
    float *S = F32, *T = F32 + 3*BIG, *Qf2 = F32 + 4*BIG, *Qf3 = F32 + 5*BIG;
#define PH_(b,i) ((b) + 2ULL*(i)*BIG)
#define PL_(b,i) ((b) + (2ULL*(i)+1)*BIG)

    cudaFuncSetAttribute(gemm_b, cudaFuncAttributeMaxDynamicSharedMemorySize, SMEM_ALLOC);

    cvt_in_k<<<dim3(8192,3), 256>>>(f[0], f[1], f[2], HF);
    WPtrs wp; for (int j = 0; j < 12; j++) wp.p[j] = W[j];
    cvt_w_k<<<dim3(1024,12), 256>>>(wp, Wb);

    // 1) preprocess: fp_i = relu(f_i Wp_i^T + b_i) -> out + split (hi+lo)
    {
        GTable t = {}; t.nb = 1;
        for (int i = 0; i < 3; i++) {
            GDesc& d = t.d[i];
            d.Ah = PH_(FIN,i); d.Al = PL_(FIN,i); d.Bh = Wb + (size_t)i*MB1;
            d.bias = bp[i]; d.relu = 1;
            d.wf32 = 1; d.Cf = out + 3072 + i*1024; d.ldcf = 6144; d.sCf = 0;
            d.wsplit = 1; d.Chi = PH_(FP,i); d.Clo = PL_(FP,i);
        }
        gemm_b<<<dim3(8,64,3), 128, SMEM_ALLOC>>>(t);
    }
    // 2) QKV projections; Q hi+lo (+fp32 for i=1,2), K hi-only, V hi-only transposed
    {
        GTable t = {}; t.nb = 1;
        for (int i = 0; i < 3; i++) {
            GDesc* d = &t.d[3*i];
            d[0].Ah = d[1].Ah = d[2].Ah = PH_(FP,i);
            d[0].Al = d[1].Al = d[2].Al = PL_(FP,i);
            d[0].Bh = Wb + (size_t)(3+3*i)*MB1;
            d[1].Bh = Wb + (size_t)(4+3*i)*MB1;
            d[2].Bh = Wb + (size_t)(5+3*i)*MB1;
            d[0].wsplit = 1; d[0].Chi = PH_(Q,i); d[0].Clo = PL_(Q,i);
            d[1].wsplit = 1; d[1].Chi = Kb + (size_t)i*BIG; d[1].Clo = nullptr;
            d[2].wsplit = 1; d[2].Chi = VT + (size_t)i*BIG; d[2].Clo = nullptr; d[2].trans = 1;
            if (i == 1) { d[0].wf32 = 1; d[0].Cf = Qf2; d[0].ldcf = 1024; }
            if (i == 2) { d[0].wf32 = 1; d[0].Cf = Qf3; d[0].ldcf = 1024; }
        }
        gemm_b<<<dim3(8,64,9), 128, SMEM_ALLOC>>>(t);
    }
    // 3) qs1 = q2 + q3 (fp32) -> split
    add_split_k<<<8192, 256>>>(Qf2, Qf3, QS1h, QS1l);

    // 4) T = q1 . k3^T (fp32)
    {
        GTable t = {}; t.nb = 8;
        GDesc& d = t.d[0];
        d.Ah = PH_(Q,0); d.Al = PL_(Q,0); d.Bh = Kb + 2*BIG;
        d.sA = 1048576; d.sB = 1048576;
        d.wf32 = 1; d.Cf = T; d.ldcf = 1024; d.sCf = 1048576;
        gemm_b<<<dim3(8,8,8), 128, SMEM_ALLOC>>>(t);
    }
    // 5) scores: s1 = qs1.k1 ; s2 = T + q3.k2 ; s3 = T + q2.k3
    {
        GTable t = {}; t.nb = 8;
        const fp16* ah[3] = { QS1h, PH_(Q,2), PH_(Q,1) };
        const fp16* al[3] = { QS1l, PL_(Q,2), PL_(Q,1) };
        const int ki[3] = { 0, 1, 2 };
        for (int m = 0; m < 3; m++) {
            GDesc& d = t.d[m];
            d.Ah = ah[m]; d.Al = al[m]; d.Bh = Kb + (size_t)ki[m]*BIG;
            d.sA = 1048576; d.sB = 1048576;
            if (m > 0) { d.AccC = T; d.sAcc = 1048576; }
            d.wf32 = 1; d.Cf = S + (size_t)m*BIG; d.ldcf = 1024; d.sCf = 1048576;
        }
        gemm_b<<<dim3(8,8,24), 128, SMEM_ALLOC>>>(t);
    }
    // 6) softmax + split P for all 3 modalities
    softmax3_k<<<24576, 256>>>(S, P);

    // 7) AV: f_mu = P_m @ V_m -> out cols [m*1024, (m+1)*1024)
    {
        GTable t = {}; t.nb = 8;
        for (int m = 0; m < 3; m++) {
            GDesc& d = t.d[m];
            d.Ah = PH_(P,m); d.Al = PL_(P,m); d.Bh = VT + (size_t)m*BIG;
            d.sA = 1048576; d.sB = 1048576;
            d.wf32 = 1; d.Cf = out + m*1024; d.ldcf = 6144; d.sCf = (long long)1024*6144;
        }
        gemm_b<<<dim3(8,8,24), 128, SMEM_ALLOC>>>(t);
    }
}

// round 13
// speedup vs baseline: 3.7865x; 1.3929x over previous
#include <cuda_runtime.h>
#include <cuda_fp16.h>
#include <cstdint>

typedef __half fp16;

#define STAGE_BYTES 49152               // Ah 16K + (Al 16K) + B 16K
#define SMEM_ALLOC (1024 + 2*STAGE_BYTES)

#define BIG 8388608ULL
#define MB1 1048576ULL

// fp16 arena: FIN 0-3 (hi), FP 3-6 (hi), Q 6-12 (hi/lo x3), K 12-15 (hi),
//             VT 15-18 (hi), QS1 18-20 (hi/lo), P 20-23 (hi), W 23..+12MB1 (hi)
__device__ fp16  g_hf[23ULL*BIG + 12ULL*MB1];
// f32 arena: S 0-3, T 3-4, Qf2 4-5, Qf3 5-6
__device__ float g_f[6ULL*BIG];

__device__ __forceinline__ uint32_t su32(const void* p){ return (uint32_t)__cvta_generic_to_shared(p); }
__device__ __forceinline__ void cp16(uint32_t s, const void* g){
    asm volatile("cp.async.cg.shared.global [%0], [%1], 16;"
        :: "r"(s), "l"((unsigned long long)__cvta_generic_to_global(g)) : "memory");
}
__device__ __forceinline__ uint32_t pk(fp16 a, fp16 b){
    return (uint32_t)__half_as_ushort(a) | ((uint32_t)__half_as_ushort(b) << 16);
}
__device__ __forceinline__ uint32_t swz(uint32_t o){ return o ^ ((o >> 3) & 0x70); }

__device__ __forceinline__ void ldsm4(uint32_t* r, uint32_t addr){
    asm volatile("ldmatrix.sync.aligned.m8n8.x4.shared.b16 {%0,%1,%2,%3}, [%4];"
        : "=r"(r[0]), "=r"(r[1]), "=r"(r[2]), "=r"(r[3]) : "r"(addr));
}
__device__ __forceinline__ void mma16816(float* d, const uint32_t* a, const uint32_t* b){
    asm volatile("mma.sync.aligned.m16n8k16.row.col.f32.f16.f16.f32 "
        "{%0,%1,%2,%3}, {%4,%5,%6,%7}, {%8,%9}, {%0,%1,%2,%3};"
        : "+f"(d[0]), "+f"(d[1]), "+f"(d[2]), "+f"(d[3])
        : "r"(a[0]), "r"(a[1]), "r"(a[2]), "r"(a[3]), "r"(b[0]), "r"(b[1]));
}

struct GDesc {
    const fp16 *Ah, *Al, *Bh;          // Al == nullptr -> 1-term GEMM
    long long sA, sB;
    const float* bias;
    const float* AccC; long long sAcc;
    float* Cf; long long sCf; int ldcf;
    fp16 *Chi, *Clo;                    // Clo==nullptr -> hi plane only
    int trans, relu, wf32, wsplit;
};
struct GTable { GDesc d[9]; int nb; };

__device__ __forceinline__ void ldfrA(uint32_t (*afb)[4], uint32_t sa, int kb,
                                      int wm, int r8, int sg)
{
#pragma unroll
    for (int mt = 0; mt < 4; mt++) {
        int row = wm + mt*16 + r8 + ((sg & 1) << 3);
        ldsm4(afb[mt], sa + swz((uint32_t)(row*128 + kb + ((sg >> 1) << 4))));
    }
}
__device__ __forceinline__ void ldfrB(uint32_t (*bfb)[4], uint32_t sb, int kb,
                                      int wn, int r8, int sg)
{
#pragma unroll
    for (int nq = 0; nq < 4; nq++) {
        int row = wn + nq*16 + r8 + ((sg >> 1) << 3);
        ldsm4(bfb[nq], sb + swz((uint32_t)(row*128 + kb + ((sg & 1) << 4))));
    }
}

// batched fp16 GEMM: C = Ah B^T (+ Al B^T) (+AccC) (+bias,relu)
// 128 threads, 4 warps, warp tile 64x64; chunk slabs: Ah @0, Al @16K, B @32K
__global__ void __launch_bounds__(128, 2) gemm_b(GTable t)
{
    extern __shared__ char smem[];
    const uint32_t tbase = (su32(smem) + 1023u) & ~1023u;
    const int tid = threadIdx.x, wid = tid >> 5, lane = tid & 31;
    const int di = blockIdx.z / t.nb, zb = blockIdx.z - di * t.nb;
    const GDesc g = t.d[di];
    const int m0 = blockIdx.y * 128, n0 = blockIdx.x * 128;
    const int wm = (wid & 1) * 64, wn = (wid >> 1) * 64;
    const int r8 = lane & 7, sg = lane >> 3;
    const bool two = (g.Al != nullptr);

    const fp16* Ah = g.Ah + (long long)zb * g.sA;
    const fp16* Al = two ? g.Al + (long long)zb * g.sA : nullptr;
    const fp16* Bh = g.Bh + (long long)zb * g.sB;

    float acc[4][8][4];
#pragma unroll
    for (int a = 0; a < 4; a++)
#pragma unroll
        for (int b = 0; b < 8; b++)
#pragma unroll
            for (int c = 0; c < 4; c++) acc[a][b][c] = 0.f;

    auto load_chunk = [&](int j) {
        const int k0 = j * 64;
        const uint32_t sa = tbase + (uint32_t)(j & 1) * STAGE_BYTES;
#pragma unroll
        for (int u = 0; u < 8; u++) {
            int s = tid + 128 * u, row = s >> 3, cs = s & 7;
            uint32_t so = swz((uint32_t)(row * 128 + cs * 16));
            const size_t go = (size_t)row * 1024 + k0 + cs * 8;
            cp16(sa + so,         Ah + (size_t)m0 * 1024 + go);
            if (two) cp16(sa + 16384 + so, Al + (size_t)m0 * 1024 + go);
            cp16(sa + 32768 + so, Bh + (size_t)n0 * 1024 + go);
        }
        asm volatile("cp.async.commit_group;" ::: "memory");
    };

    load_chunk(0);

    uint32_t af[2][4][4], bfr[2][4][4];

    for (int i = 0; i < 16; i++) {
        asm volatile("cp.async.wait_group 0;" ::: "memory");
        __syncthreads();
        if (i + 1 < 16) load_chunk(i + 1);

        const uint32_t sa  = tbase + (uint32_t)(i & 1) * STAGE_BYTES;
        const uint32_t sal = sa + 16384, sb = sa + 32768;

        if (two) {
            // 8 micro-iters: it -> ks = it>>1, A-plane = (it&1) ? lo : hi
            ldfrA(af[0], sa, 0, wm, r8, sg);
            ldfrB(bfr[0], sb, 0, wn, r8, sg);
#pragma unroll
            for (int it = 0; it < 8; it++) {
                const int cur = it & 1;
                const int ks = it >> 1;
                if (it < 7) {
                    const int nit = it + 1, nks = nit >> 1;
                    ldfrA(af[cur ^ 1], (nit & 1) ? sal : sa, nks * 32, wm, r8, sg);
                    if ((nit & 1) == 0) ldfrB(bfr[nks & 1], sb, nks * 32, wn, r8, sg);
                }
                const uint32_t (*bm)[4] = bfr[ks & 1];
#pragma unroll
                for (int mt = 0; mt < 4; mt++)
#pragma unroll
                    for (int nq = 0; nq < 4; nq++) {
                        mma16816(acc[mt][2*nq],     af[cur][mt], bm[nq]);
                        mma16816(acc[mt][2*nq + 1], af[cur][mt], bm[nq] + 2);
                    }
            }
        } else {
            // 1-term: 4 k-steps, double-buffered fragments
            ldfrA(af[0], sa, 0, wm, r8, sg);
            ldfrB(bfr[0], sb, 0, wn, r8, sg);
#pragma unroll
            for (int ks = 0; ks < 4; ks++) {
                const int cur = ks & 1;
                if (ks < 3) {
                    ldfrA(af[cur ^ 1], sa, (ks + 1) * 32, wm, r8, sg);
                    ldfrB(bfr[cur ^ 1], sb, (ks + 1) * 32, wn, r8, sg);
                }
#pragma unroll
                for (int mt = 0; mt < 4; mt++)
#pragma unroll
                    for (int nq = 0; nq < 4; nq++) {
                        mma16816(acc[mt][2*nq],     af[cur][mt], bfr[cur][nq]);
                        mma16816(acc[mt][2*nq + 1], af[cur][mt], bfr[cur][nq] + 2);
                    }
            }
        }
    }

#pragma unroll
    for (int mt = 0; mt < 4; mt++)
#pragma unroll
        for (int ri = 0; ri < 2; ri++) {
            const long long rg = m0 + wm + mt * 16 + ri * 8 + (lane >> 2);
            const float* accp = g.AccC ? g.AccC + (long long)zb * g.sAcc + rg * 1024 : nullptr;
            float* cf = g.wf32 ? g.Cf + (long long)zb * g.sCf + rg * (long long)g.ldcf : nullptr;
            fp16 *chi = nullptr, *clo = nullptr;
            long long bb = 0, tb = 0;
            if (g.wsplit) {
                if (g.trans) { bb = (rg >> 10) * 1048576LL; tb = rg & 1023LL; }
                else {
                    chi = g.Chi + rg * 1024LL;
                    if (g.Clo) clo = g.Clo + rg * 1024LL;
                }
            }
#pragma unroll
            for (int nt = 0; nt < 8; nt++) {
                const int c = n0 + wn + nt * 8 + (lane & 3) * 2;
                float v0 = acc[mt][nt][ri * 2];
                float v1 = acc[mt][nt][ri * 2 + 1];
                if (accp) { float2 tv = *(const float2*)(accp + c); v0 += tv.x; v1 += tv.y; }
                if (g.relu) {
                    v0 = fmaxf(v0 + g.bias[c], 0.f);
                    v1 = fmaxf(v1 + g.bias[c + 1], 0.f);
                }
                if (cf) *(float2*)(cf + c) = make_float2(v0, v1);
                if (g.wsplit) {
                    fp16 h0 = __float2half_rn(v0), h1 = __float2half_rn(v1);
                    if (g.trans) {
                        g.Chi[bb + (long long)c * 1024 + tb] = h0;
                        g.Chi[bb + (long long)(c + 1) * 1024 + tb] = h1;
                    } else {
                        *(uint32_t*)(chi + c) = pk(h0, h1);
                        if (clo) {
                            fp16 l0 = __float2half_rn(v0 - __half2float(h0));
                            fp16 l1 = __float2half_rn(v1 - __half2float(h1));
                            *(uint32_t*)(clo + c) = pk(l0, l1);
                        }
                    }
                }
            }
        }
}

__device__ __forceinline__ void split4(float4 v, uint2& h, uint2& l)
{
    fp16 h0=__float2half_rn(v.x), h1=__float2half_rn(v.y), h2=__float2half_rn(v.z), h3=__float2half_rn(v.w);
    fp16 l0=__float2half_rn(v.x-__half2float(h0)), l1=__float2half_rn(v.y-__half2float(h1));
    fp16 l2=__float2half_rn(v.z-__half2float(h2)), l3=__float2half_rn(v.w-__half2float(h3));
    h = make_uint2(pk(h0,h1), pk(h2,h3));
    l = make_uint2(pk(l0,l1), pk(l2,l3));
}

// input convert: hi plane only
__global__ void cvt_in_k(const float* f0, const float* f1, const float* f2, fp16* base)
{
    const float* src = (blockIdx.y == 0) ? f0 : (blockIdx.y == 1) ? f1 : f2;
    size_t i = (size_t)blockIdx.x * 256 + threadIdx.x;
    float4 v = ((const float4*)src)[i];
    uint2 h = make_uint2(pk(__float2half_rn(v.x), __float2half_rn(v.y)),
                         pk(__float2half_rn(v.z), __float2half_rn(v.w)));
    ((uint2*)(base + (size_t)blockIdx.y*BIG))[i] = h;
}

struct WPtrs { const float* p[12]; };
__global__ void cvt_w_k(WPtrs w, fp16* wb)   // hi plane only
{
    size_t i = (size_t)blockIdx.x * 256 + threadIdx.x;
    float4 v = ((const float4*)w.p[blockIdx.y])[i];
    uint2 h = make_uint2(pk(__float2half_rn(v.x), __float2half_rn(v.y)),
                         pk(__float2half_rn(v.z), __float2half_rn(v.w)));
    ((uint2*)(wb + (size_t)blockIdx.y*MB1))[i] = h;
}

__global__ void add_split_k(const float* __restrict__ a, const float* __restrict__ b,
                            fp16* __restrict__ hi, fp16* __restrict__ lo)
{
    size_t i = (size_t)blockIdx.x * 256 + threadIdx.x;
    float4 x = ((const float4*)a)[i];
    float4 y = ((const float4*)b)[i];
    x.x += y.x; x.y += y.y; x.z += y.z; x.w += y.w;
    uint2 h, l;
    split4(x, h, l);
    ((uint2*)hi)[i] = h;
    ((uint2*)lo)[i] = l;
}

// softmax over rows of 1024; grid.x = 3*8192; P hi-only
__global__ void softmax3_k(const float* __restrict__ S, fp16* __restrict__ P)
{
    __shared__ float red[256];
    const int m = blockIdx.x >> 13;
    const size_t row = blockIdx.x & 8191;
    const float* p = S + (size_t)m * BIG + row * 1024;
    int tid = threadIdx.x;
    float4 v = ((const float4*)p)[tid];
    float mx = fmaxf(fmaxf(v.x, v.y), fmaxf(v.z, v.w));
    red[tid] = mx; __syncthreads();
    for (int s = 128; s > 0; s >>= 1) { if (tid < s) red[tid] = fmaxf(red[tid], red[tid+s]); __syncthreads(); }
    mx = red[0]; __syncthreads();
    v.x = __expf(v.x-mx); v.y = __expf(v.y-mx); v.z = __expf(v.z-mx); v.w = __expf(v.w-mx);
    red[tid] = v.x + v.y + v.z + v.w; __syncthreads();
    for (int s = 128; s > 0; s >>= 1) { if (tid < s) red[tid] += red[tid+s]; __syncthreads(); }
    float inv = 1.f / red[0];
    v.x *= inv; v.y *= inv; v.z *= inv; v.w *= inv;
    uint2 h = make_uint2(pk(__float2half_rn(v.x), __float2half_rn(v.y)),
                         pk(__float2half_rn(v.z), __float2half_rn(v.w)));
    ((uint2*)(P + (size_t)m*BIG))[row * 256 + tid] = h;
}

extern "C" void kernel_launch(void* const* d_in, const int* in_sizes, int n_in,
                              void* d_out, int out_size)
{
    const float* f[3]  = { (const float*)d_in[0], (const float*)d_in[1], (const float*)d_in[2] };
    const float* W[12]; for (int j = 0; j < 12; j++) W[j] = (const float*)d_in[3 + j];
    const float* bp[3] = { (const float*)d_in[15], (const float*)d_in[16], (const float*)d_in[17] };
    float* out = (float*)d_out;

    fp16* HF = nullptr;  cudaGetSymbolAddress((void**)&HF, g_hf);
    float* F32 = nullptr; cudaGetSymbolAddress((void**)&F32, g_f);

    fp16 *FIN = HF, *FP = HF + 3*BIG, *Q = HF + 6*BIG;
    fp16 *Kb = HF + 12*BIG, *VT = HF + 15*BIG;
    fp16 *QS1h = HF + 18*BIG, *QS1l = HF + 19*BIG, *P = HF + 20*BIG, *Wb = HF + 23*BIG;
    float *S = F32, *T = F32 + 3*BIG, *Qf2 = F32 + 4*BIG, *Qf3 = F32 + 5*BIG;
#define QH_(i) (Q + 2ULL*(i)*BIG)
#define QL_(i) (Q + (2ULL*(i)+1)*BIG)

    cudaFuncSetAttribute(gemm_b, cudaFuncAttributeMaxDynamicSharedMemorySize, SMEM_ALLOC);

    cvt_in_k<<<dim3(8192,3), 256>>>(f[0], f[1], f[2], FIN);
    WPtrs wp; for (int j = 0; j < 12; j++) wp.p[j] = W[j];
    cvt_w_k<<<dim3(1024,12), 256>>>(wp, Wb);

    // 1) preprocess (1-term): fp_i = relu(f_i Wp_i^T + b_i) -> out + FP hi
    {
        GTable t = {}; t.nb = 1;
        for (int i = 0; i < 3; i++) {
            GDesc& d = t.d[i];
            d.Ah = FIN + (size_t)i*BIG; d.Al = nullptr; d.Bh = Wb + (size_t)i*MB1;
            d.bias = bp[i]; d.relu = 1;
            d.wf32 = 1; d.Cf = out + 3072 + i*1024; d.ldcf = 6144; d.sCf = 0;
            d.wsplit = 1; d.Chi = FP + (size_t)i*BIG; d.Clo = nullptr;
        }
        gemm_b<<<dim3(8,64,3), 128, SMEM_ALLOC>>>(t);
    }
    // 2) QKV (1-term): Q hi+lo (+fp32 for i=1,2), K hi, V hi transposed
    {
        GTable t = {}; t.nb = 1;
        for (int i = 0; i < 3; i++) {
            GDesc* d = &t.d[3*i];
            d[0].Ah = d[1].Ah = d[2].Ah = FP + (size_t)i*BIG;
            d[0].Bh = Wb + (size_t)(3+3*i)*MB1;
            d[1].Bh = Wb + (size_t)(4+3*i)*MB1;
            d[2].Bh = Wb + (size_t)(5+3*i)*MB1;
            d[0].wsplit = 1; d[0].Chi = QH_(i); d[0].Clo = QL_(i);
            d[1].wsplit = 1; d[1].Chi = Kb + (size_t)i*BIG; d[1].Clo = nullptr;
            d[2].wsplit = 1; d[2].Chi = VT + (size_t)i*BIG; d[2].Clo = nullptr; d[2].trans = 1;
            if (i == 1) { d[0].wf32 = 1; d[0].Cf = Qf2; d[0].ldcf = 1024; }
            if (i == 2) { d[0].wf32 = 1; d[0].Cf = Qf3; d[0].ldcf = 1024; }
        }
        gemm_b<<<dim3(8,64,9), 128, SMEM_ALLOC>>>(t);
    }
    // 3) qs1 = q2 + q3 (fp32) -> hi+lo
    add_split_k<<<8192, 256>>>(Qf2, Qf3, QS1h, QS1l);

    // 4) T = q1 . k3^T (2-term, fp32)
    {
        GTable t = {}; t.nb = 8;
        GDesc& d = t.d[0];
        d.Ah = QH_(0); d.Al = QL_(0); d.Bh = Kb + 2*BIG;
        d.sA = 1048576; d.sB = 1048576;
        d.wf32 = 1; d.Cf = T; d.ldcf = 1024; d.sCf = 1048576;
        gemm_b<<<dim3(8,8,8), 128, SMEM_ALLOC>>>(t);
    }
    // 5) scores (2-term): s1 = qs1.k1 ; s2 = T + q3.k2 ; s3 = T + q2.k3
    {
        GTable t = {}; t.nb = 8;
        const fp16* ah[3] = { QS1h, QH_(2), QH_(1) };
        const fp16* al[3] = { QS1l, QL_(2), QL_(1) };
        const int ki[3] = { 0, 1, 2 };
        for (int m = 0; m < 3; m++) {
            GDesc& d = t.d[m];
            d.Ah = ah[m]; d.Al = al[m]; d.Bh = Kb + (size_t)ki[m]*BIG;
            d.sA = 1048576; d.sB = 1048576;
            if (m > 0) { d.AccC = T; d.sAcc = 1048576; }
            d.wf32 = 1; d.Cf = S + (size_t)m*BIG; d.ldcf = 1024; d.sCf = 1048576;
        }
        gemm_b<<<dim3(8,8,24), 128, SMEM_ALLOC>>>(t);
    }
    // 6) softmax -> P hi
    softmax3_k<<<24576, 256>>>(S, P);

    // 7) AV (1-term): f_mu = P_m @ V_m -> out cols [m*1024, (m+1)*1024)
    {
        GTable t = {}; t.nb = 8;
        for (int m = 0; m < 3; m++) {
            GDesc& d = t.d[m];
            d.Ah = P + (size_t)m*BIG; d.Al = nullptr; d.Bh = VT + (size_t)m*BIG;
            d.sA = 1048576; d.sB = 1048576;
            d.wf32 = 1; d.Cf = out + m*1024; d.ldcf = 6144; d.sCf = (long long)1024*6144;
        }
        gemm_b<<<dim3(8,8,24), 128, SMEM_ALLOC>>>(t);
    }
}

// round 14
// speedup vs baseline: 4.2674x; 1.1270x over previous
#include <cuda_runtime.h>
#include <cuda_fp16.h>
#include <cstdint>

typedef __half fp16;

#define STAGE_BYTES 32768               // A 16K + B 16K
#define SMEM_ALLOC (1024 + 3*STAGE_BYTES)

#define BIG 8388608ULL
#define MB1 1048576ULL

// fp16 arena: FIN 0-3, FP 3-6, Q 6-9, K 9-12, VT 12-15, QS1 15, P 16-19, W 19..+12MB1
__device__ fp16  g_hf[19ULL*BIG + 12ULL*MB1];
// f32 arena: S 0-3, T 3-4, Qf2 4-5, Qf3 5-6
__device__ float g_f[6ULL*BIG];

__device__ __forceinline__ uint32_t su32(const void* p){ return (uint32_t)__cvta_generic_to_shared(p); }
__device__ __forceinline__ void cp16(uint32_t s, const void* g){
    asm volatile("cp.async.cg.shared.global [%0], [%1], 16;"
        :: "r"(s), "l"((unsigned long long)__cvta_generic_to_global(g)) : "memory");
}
__device__ __forceinline__ uint32_t pk(fp16 a, fp16 b){
    return (uint32_t)__half_as_ushort(a) | ((uint32_t)__half_as_ushort(b) << 16);
}
__device__ __forceinline__ uint32_t swz(uint32_t o){ return o ^ ((o >> 3) & 0x70); }

__device__ __forceinline__ void ldsm4(uint32_t* r, uint32_t addr){
    asm volatile("ldmatrix.sync.aligned.m8n8.x4.shared.b16 {%0,%1,%2,%3}, [%4];"
        : "=r"(r[0]), "=r"(r[1]), "=r"(r[2]), "=r"(r[3]) : "r"(addr));
}
__device__ __forceinline__ void mma16816(float* d, const uint32_t* a, const uint32_t* b){
    asm volatile("mma.sync.aligned.m16n8k16.row.col.f32.f16.f16.f32 "
        "{%0,%1,%2,%3}, {%4,%5,%6,%7}, {%8,%9}, {%0,%1,%2,%3};"
        : "+f"(d[0]), "+f"(d[1]), "+f"(d[2]), "+f"(d[3])
        : "r"(a[0]), "r"(a[1]), "r"(a[2]), "r"(a[3]), "r"(b[0]), "r"(b[1]));
}

struct GDesc {
    const fp16 *Ah, *Bh;
    long long sA, sB;
    const float* bias;
    const float* AccC; long long sAcc;
    float* Cf; long long sCf; int ldcf;
    fp16 *Chi;
    int trans, relu, wf32, wsplit;
};
struct GTable { GDesc d[9]; int nb; };

__device__ __forceinline__ void ldfrA(uint32_t (*afb)[4], uint32_t sa, int kb,
                                      int wm, int r8, int sg)
{
#pragma unroll
    for (int mt = 0; mt < 4; mt++) {
        int row = wm + mt*16 + r8 + ((sg & 1) << 3);
        ldsm4(afb[mt], sa + swz((uint32_t)(row*128 + kb + ((sg >> 1) << 4))));
    }
}
__device__ __forceinline__ void ldfrB(uint32_t (*bfb)[4], uint32_t sb, int kb,
                                      int wn, int r8, int sg)
{
#pragma unroll
    for (int nq = 0; nq < 4; nq++) {
        int row = wn + nq*16 + r8 + ((sg >> 1) << 3);
        ldsm4(bfb[nq], sb + swz((uint32_t)(row*128 + kb + ((sg & 1) << 4))));
    }
}

// batched fp16 GEMM: C = A B^T (+AccC) (+bias,relu); 128 thr, 4 warps 64x64,
// 3-stage 32KB ring, prefetch depth 2
__global__ void __launch_bounds__(128, 2) gemm_b(GTable t)
{
    extern __shared__ char smem[];
    const uint32_t tbase = (su32(smem) + 1023u) & ~1023u;
    const int tid = threadIdx.x, wid = tid >> 5, lane = tid & 31;
    const int di = blockIdx.z / t.nb, zb = blockIdx.z - di * t.nb;
    const GDesc g = t.d[di];
    const int m0 = blockIdx.y * 128, n0 = blockIdx.x * 128;
    const int wm = (wid & 1) * 64, wn = (wid >> 1) * 64;
    const int r8 = lane & 7, sg = lane >> 3;

    const fp16* Ah = g.Ah + (long long)zb * g.sA;
    const fp16* Bh = g.Bh + (long long)zb * g.sB;

    float acc[4][8][4];
#pragma unroll
    for (int a = 0; a < 4; a++)
#pragma unroll
        for (int b = 0; b < 8; b++)
#pragma unroll
            for (int c = 0; c < 4; c++) acc[a][b][c] = 0.f;

    auto load_chunk = [&](int j) {
        const int k0 = j * 64;
        const uint32_t sa = tbase + (uint32_t)(j % 3) * STAGE_BYTES;
#pragma unroll
        for (int u = 0; u < 8; u++) {
            int s = tid + 128 * u, row = s >> 3, cs = s & 7;
            uint32_t so = swz((uint32_t)(row * 128 + cs * 16));
            const size_t go = (size_t)row * 1024 + k0 + cs * 8;
            cp16(sa + so,         Ah + (size_t)m0 * 1024 + go);
            cp16(sa + 16384 + so, Bh + (size_t)n0 * 1024 + go);
        }
        asm volatile("cp.async.commit_group;" ::: "memory");
    };

    load_chunk(0);
    load_chunk(1);

    uint32_t af[2][4][4], bfr[2][4][4];

#pragma unroll 1
    for (int i = 0; i < 16; i++) {
        if (i + 1 < 16) asm volatile("cp.async.wait_group 1;" ::: "memory");
        else            asm volatile("cp.async.wait_group 0;" ::: "memory");
        __syncthreads();
        if (i + 2 < 16) load_chunk(i + 2);

        const uint32_t sa = tbase + (uint32_t)(i % 3) * STAGE_BYTES;
        const uint32_t sb = sa + 16384;

        ldfrA(af[0], sa, 0, wm, r8, sg);
        ldfrB(bfr[0], sb, 0, wn, r8, sg);
#pragma unroll
        for (int ks = 0; ks < 4; ks++) {
            const int cur = ks & 1;
            if (ks < 3) {
                ldfrA(af[cur ^ 1], sa, (ks + 1) * 32, wm, r8, sg);
                ldfrB(bfr[cur ^ 1], sb, (ks + 1) * 32, wn, r8, sg);
            }
#pragma unroll
            for (int mt = 0; mt < 4; mt++)
#pragma unroll
                for (int nq = 0; nq < 4; nq++) {
                    mma16816(acc[mt][2*nq],     af[cur][mt], bfr[cur][nq]);
                    mma16816(acc[mt][2*nq + 1], af[cur][mt], bfr[cur][nq] + 2);
                }
        }
    }

#pragma unroll
    for (int mt = 0; mt < 4; mt++)
#pragma unroll
        for (int ri = 0; ri < 2; ri++) {
            const long long rg = m0 + wm + mt * 16 + ri * 8 + (lane >> 2);
            const float* accp = g.AccC ? g.AccC + (long long)zb * g.sAcc + rg * 1024 : nullptr;
            float* cf = g.wf32 ? g.Cf + (long long)zb * g.sCf + rg * (long long)g.ldcf : nullptr;
            fp16 *chi = nullptr;
            long long bb = 0, tb = 0;
            if (g.wsplit) {
                if (g.trans) { bb = (rg >> 10) * 1048576LL; tb = rg & 1023LL; }
                else         { chi = g.Chi + rg * 1024LL; }
            }
#pragma unroll
            for (int nt = 0; nt < 8; nt++) {
                const int c = n0 + wn + nt * 8 + (lane & 3) * 2;
                float v0 = acc[mt][nt][ri * 2];
                float v1 = acc[mt][nt][ri * 2 + 1];
                if (accp) { float2 tv = *(const float2*)(accp + c); v0 += tv.x; v1 += tv.y; }
                if (g.relu) {
                    v0 = fmaxf(v0 + g.bias[c], 0.f);
                    v1 = fmaxf(v1 + g.bias[c + 1], 0.f);
                }
                if (cf) *(float2*)(cf + c) = make_float2(v0, v1);
                if (g.wsplit) {
                    fp16 h0 = __float2half_rn(v0), h1 = __float2half_rn(v1);
                    if (g.trans) {
                        g.Chi[bb + (long long)c * 1024 + tb] = h0;
                        g.Chi[bb + (long long)(c + 1) * 1024 + tb] = h1;
                    } else {
                        *(uint32_t*)(chi + c) = pk(h0, h1);
                    }
                }
            }
        }
}

// input convert: fp16
__global__ void cvt_in_k(const float* f0, const float* f1, const float* f2, fp16* base)
{
    const float* src = (blockIdx.y == 0) ? f0 : (blockIdx.y == 1) ? f1 : f2;
    size_t i = (size_t)blockIdx.x * 256 + threadIdx.x;
    float4 v = ((const float4*)src)[i];
    uint2 h = make_uint2(pk(__float2half_rn(v.x), __float2half_rn(v.y)),
                         pk(__float2half_rn(v.z), __float2half_rn(v.w)));
    ((uint2*)(base + (size_t)blockIdx.y*BIG))[i] = h;
}

struct WPtrs { const float* p[12]; };
__global__ void cvt_w_k(WPtrs w, fp16* wb)
{
    size_t i = (size_t)blockIdx.x * 256 + threadIdx.x;
    float4 v = ((const float4*)w.p[blockIdx.y])[i];
    uint2 h = make_uint2(pk(__float2half_rn(v.x), __float2half_rn(v.y)),
                         pk(__float2half_rn(v.z), __float2half_rn(v.w)));
    ((uint2*)(wb + (size_t)blockIdx.y*MB1))[i] = h;
}

__global__ void add_h_k(const float* __restrict__ a, const float* __restrict__ b,
                        fp16* __restrict__ hi)
{
    size_t i = (size_t)blockIdx.x * 256 + threadIdx.x;
    float4 x = ((const float4*)a)[i];
    float4 y = ((const float4*)b)[i];
    x.x += y.x; x.y += y.y; x.z += y.z; x.w += y.w;
    uint2 h = make_uint2(pk(__float2half_rn(x.x), __float2half_rn(x.y)),
                         pk(__float2half_rn(x.z), __float2half_rn(x.w)));
    ((uint2*)hi)[i] = h;
}

// softmax over rows of 1024; grid.x = 3*8192; P fp16
__global__ void softmax3_k(const float* __restrict__ S, fp16* __restrict__ P)
{
    __shared__ float red[256];
    const int m = blockIdx.x >> 13;
    const size_t row = blockIdx.x & 8191;
    const float* p = S + (size_t)m * BIG + row * 1024;
    int tid = threadIdx.x;
    float4 v = ((const float4*)p)[tid];
    float mx = fmaxf(fmaxf(v.x, v.y), fmaxf(v.z, v.w));
    red[tid] = mx; __syncthreads();
    for (int s = 128; s > 0; s >>= 1) { if (tid < s) red[tid] = fmaxf(red[tid], red[tid+s]); __syncthreads(); }
    mx = red[0]; __syncthreads();
    v.x = __expf(v.x-mx); v.y = __expf(v.y-mx); v.z = __expf(v.z-mx); v.w = __expf(v.w-mx);
    red[tid] = v.x + v.y + v.z + v.w; __syncthreads();
    for (int s = 128; s > 0; s >>= 1) { if (tid < s) red[tid] += red[tid+s]; __syncthreads(); }
    float inv = 1.f / red[0];
    v.x *= inv; v.y *= inv; v.z *= inv; v.w *= inv;
    uint2 h = make_uint2(pk(__float2half_rn(v.x), __float2half_rn(v.y)),
                         pk(__float2half_rn(v.z), __float2half_rn(v.w)));
    ((uint2*)(P + (size_t)m*BIG))[row * 256 + tid] = h;
}

extern "C" void kernel_launch(void* const* d_in, const int* in_sizes, int n_in,
                              void* d_out, int out_size)
{
    const float* f[3]  = { (const float*)d_in[0], (const float*)d_in[1], (const float*)d_in[2] };
    const float* W[12]; for (int j = 0; j < 12; j++) W[j] = (const float*)d_in[3 + j];
    const float* bp[3] = { (const float*)d_in[15], (const float*)d_in[16], (const float*)d_in[17] };
    float* out = (float*)d_out;

    fp16* HF = nullptr;  cudaGetSymbolAddress((void**)&HF, g_hf);
    float* F32 = nullptr; cudaGetSymbolAddress((void**)&F32, g_f);

    fp16 *FIN = HF, *FP = HF + 3*BIG, *Qh = HF + 6*BIG;
    fp16 *Kb = HF + 9*BIG, *VT = HF + 12*BIG;
    fp16 *QS1 = HF + 15*BIG, *P = HF + 16*BIG, *Wb = HF + 19*BIG;
    float *S = F32, *T = F32 + 3*BIG, *Qf2 = F32 + 4*BIG, *Qf3 = F32 + 5*BIG;

    cudaFuncSetAttribute(gemm_b, cudaFuncAttributeMaxDynamicSharedMemorySize, SMEM_ALLOC);

    cvt_in_k<<<dim3(8192,3), 256>>>(f[0], f[1], f[2], FIN);
    WPtrs wp; for (int j = 0; j < 12; j++) wp.p[j] = W[j];
    cvt_w_k<<<dim3(1024,12), 256>>>(wp, Wb);

    // 1) preprocess: fp_i = relu(f_i Wp_i^T + b_i) -> out + FP fp16
    {
        GTable t = {}; t.nb = 1;
        for (int i = 0; i < 3; i++) {
            GDesc& d = t.d[i];
            d.Ah = FIN + (size_t)i*BIG; d.Bh = Wb + (size_t)i*MB1;
            d.bias = bp[i]; d.relu = 1;
            d.wf32 = 1; d.Cf = out + 3072 + i*1024; d.ldcf = 6144; d.sCf = 0;
            d.wsplit = 1; d.Chi = FP + (size_t)i*BIG;
        }
        gemm_b<<<dim3(8,64,3), 128, SMEM_ALLOC>>>(t);
    }
    // 2) QKV: Q fp16 (+fp32 for i=1,2), K fp16, V fp16 transposed
    {
        GTable t = {}; t.nb = 1;
        for (int i = 0; i < 3; i++) {
            GDesc* d = &t.d[3*i];
            d[0].Ah = d[1].Ah = d[2].Ah = FP + (size_t)i*BIG;
            d[0].Bh = Wb + (size_t)(3+3*i)*MB1;
            d[1].Bh = Wb + (size_t)(4+3*i)*MB1;
            d[2].Bh = Wb + (size_t)(5+3*i)*MB1;
            d[0].wsplit = 1; d[0].Chi = Qh + (size_t)i*BIG;
            d[1].wsplit = 1; d[1].Chi = Kb + (size_t)i*BIG;
            d[2].wsplit = 1; d[2].Chi = VT + (size_t)i*BIG; d[2].trans = 1;
            if (i == 1) { d[0].wf32 = 1; d[0].Cf = Qf2; d[0].ldcf = 1024; }
            if (i == 2) { d[0].wf32 = 1; d[0].Cf = Qf3; d[0].ldcf = 1024; }
        }
        gemm_b<<<dim3(8,64,9), 128, SMEM_ALLOC>>>(t);
    }
    // 3) qs1 = fp16(q2 + q3)
    add_h_k<<<8192, 256>>>(Qf2, Qf3, QS1);

    // 4) T = q1 . k3^T (fp32)
    {
        GTable t = {}; t.nb = 8;
        GDesc& d = t.d[0];
        d.Ah = Qh; d.Bh = Kb + 2*BIG;
        d.sA = 1048576; d.sB = 1048576;
        d.wf32 = 1; d.Cf = T; d.ldcf = 1024; d.sCf = 1048576;
        gemm_b<<<dim3(8,8,8), 128, SMEM_ALLOC>>>(t);
    }
    // 5) scores: s1 = qs1.k1 ; s2 = T + q3.k2 ; s3 = T + q2.k3
    {
        GTable t = {}; t.nb = 8;
        const fp16* ah[3] = { QS1, Qh + 2*BIG, Qh + 1*BIG };
        const int ki[3] = { 0, 1, 2 };
        for (int m = 0; m < 3; m++) {
            GDesc& d = t.d[m];
            d.Ah = ah[m]; d.Bh = Kb + (size_t)ki[m]*BIG;
            d.sA = 1048576; d.sB = 1048576;
            if (m > 0) { d.AccC = T; d.sAcc = 1048576; }
            d.wf32 = 1; d.Cf = S + (size_t)m*BIG; d.ldcf = 1024; d.sCf = 1048576;
        }
        gemm_b<<<dim3(8,8,24), 128, SMEM_ALLOC>>>(t);
    }
    // 6) softmax -> P fp16
    softmax3_k<<<24576, 256>>>(S, P);

    // 7) AV: f_mu = P_m @ V_m -> out cols [m*1024, (m+1)*1024)
    {
        GTable t = {}; t.nb = 8;
        for (int m = 0; m < 3; m++) {
            GDesc& d = t.d[m];
            d.Ah = P + (size_t)m*BIG; d.Bh = VT + (size_t)m*BIG;
            d.sA = 1048576; d.sB = 1048576;
            d.wf32 = 1; d.Cf = out + m*1024; d.ldcf = 6144; d.sCf = (long long)1024*6144;
        }
        gemm_b<<<dim3(8,8,24), 128, SMEM_ALLOC>>>(t);
    }
}